// round 13
// baseline (speedup 1.0000x reference)
#include <cuda_runtime.h>
#include <math.h>
#include <stdint.h>

#define NB 8
#define NS 1024
#define ND 512
#define NH 8
#define NL 6
#define NF 2048
#define NV 512
#define NM (NB*NS)

#define SZ_HD   ((size_t)NM*ND)
#define SZ_QKV  ((size_t)NM*1536)
#define SZ_FF   ((size_t)NM*NF)
#define SZ_WQKV ((size_t)NL*512*1536)
#define SZ_WO   ((size_t)NL*512*512)
#define SZ_W1   ((size_t)NL*512*2048)
#define SZ_W2   ((size_t)NL*2048*512)
#define SZ_WOUT ((size_t)512*512)
#define SZ_BQKV ((size_t)NL*1536)

__device__ float g_scratch[4*SZ_HD + SZ_QKV + SZ_FF + SZ_WQKV + SZ_WO +
                           SZ_W1 + SZ_W2 + SZ_WOUT + SZ_BQKV];

// ---------------------------------------------------------------------------
// Helpers
// ---------------------------------------------------------------------------
__device__ __forceinline__ float tf32r(float x) {
    uint32_t y;
    asm("cvt.rna.tf32.f32 %0, %1;" : "=r"(y) : "f"(x));
    return __uint_as_float(y);
}

// quad-K permutation: within each 16-k block, k -> (k&3)*4 + (k&15)/4
__device__ __forceinline__ int qposf(int k) {
    int k16 = k & 15;
    return (k & ~15) + ((k16 & 3) << 2) + (k16 >> 2);
}

__device__ __forceinline__ void mma_tf32(float c[4], const float a[4],
                                         const float b[2]) {
    asm volatile(
        "mma.sync.aligned.m16n8k8.row.col.f32.tf32.tf32.f32 "
        "{%0,%1,%2,%3}, {%4,%5,%6,%7}, {%8,%9}, {%0,%1,%2,%3};\n"
        : "+f"(c[0]), "+f"(c[1]), "+f"(c[2]), "+f"(c[3])
        : "r"(__float_as_uint(a[0])), "r"(__float_as_uint(a[1])),
          "r"(__float_as_uint(a[2])), "r"(__float_as_uint(a[3])),
          "r"(__float_as_uint(b[0])), "r"(__float_as_uint(b[1])));
}

__device__ __forceinline__ void cpa16(uint32_t dst, const void* src) {
    asm volatile("cp.async.ca.shared.global [%0], [%1], 16;\n"
                 :: "r"(dst), "l"(src));
}
__device__ __forceinline__ void cpa_commit() {
    asm volatile("cp.async.commit_group;\n" ::);
}
__device__ __forceinline__ void cpa_wait1() {
    asm volatile("cp.async.wait_group 1;\n" ::);
}

// ---------------------------------------------------------------------------
// Pre-pass: tf32-rounded transposes -> [N][K] K-major with quad-K permutation
// ---------------------------------------------------------------------------
__global__ void trans_gen(const float* __restrict__ src, float* __restrict__ dst,
                          int R, int C) {
    __shared__ float t[32][33];
    size_t mo = (size_t)blockIdx.z * R * C;
    int c0 = blockIdx.x * 32, r0 = blockIdx.y * 32;
    #pragma unroll
    for (int i = threadIdx.y; i < 32; i += 8)
        t[i][threadIdx.x] = src[mo + (size_t)(r0 + i) * C + c0 + threadIdx.x];
    __syncthreads();
    #pragma unroll
    for (int i = threadIdx.y; i < 32; i += 8)
        dst[mo + (size_t)(c0 + i) * R + qposf(r0 + threadIdx.x)] =
            tf32r(t[threadIdx.x][i]);
}

__global__ void trans_qkv(const float* __restrict__ Wq, const float* __restrict__ Wk,
                          const float* __restrict__ Wv, float* __restrict__ dst) {
    __shared__ float t[32][33];
    int z = blockIdx.z;
    int l = z / 3, j = z % 3;
    const float* src = (j == 0) ? Wq : (j == 1) ? Wk : Wv;
    src += (size_t)l * 262144;
    float* d = dst + (size_t)l * 786432 + (size_t)j * 262144;
    int c0 = blockIdx.x * 32, r0 = blockIdx.y * 32;
    #pragma unroll
    for (int i = threadIdx.y; i < 32; i += 8)
        t[i][threadIdx.x] = src[(size_t)(r0 + i) * 512 + c0 + threadIdx.x];
    __syncthreads();
    #pragma unroll
    for (int i = threadIdx.y; i < 32; i += 8)
        d[(size_t)(c0 + i) * 512 + qposf(r0 + threadIdx.x)] =
            tf32r(t[threadIdx.x][i]);
}

__global__ void pack_qkv_b(const float* __restrict__ bq, const float* __restrict__ bk,
                           const float* __restrict__ bv, float* __restrict__ dst) {
    int i = blockIdx.x * 256 + threadIdx.x;
    int l = i / 1536;
    int j = i % 1536;
    const float* src = (j < 512) ? bq : (j < 1024) ? bk : bv;
    dst[i] = src[l * 512 + (j & 511)];
}

// ---------------------------------------------------------------------------
// Embedding: h (row-major fp32) + h_r (quad-K, tf32-rounded)
// ---------------------------------------------------------------------------
__global__ void embed_kernel(const int* __restrict__ ids,
                             const float* __restrict__ emb,
                             const float* __restrict__ pe,
                             float* __restrict__ h, float* __restrict__ hr)
{
    int i = blockIdx.x * blockDim.x + threadIdx.x;
    int row = i >> 7;
    int d4  = (i & 127) << 2;
    int s   = row & (NS - 1);
    int tok = ids[row];
    const float SC = 22.62741699796952f;
    float4 e = *(const float4*)(emb + (size_t)tok * ND + d4);
    float4 p = *(const float4*)(pe  + (size_t)s   * ND + d4);
    float4 r;
    r.x = e.x * SC + p.x; r.y = e.y * SC + p.y;
    r.z = e.z * SC + p.z; r.w = e.w * SC + p.w;
    *(float4*)(h + (size_t)row * ND + d4) = r;
    float* hp = hr + (size_t)row * ND;
    hp[qposf(d4 + 0)] = tf32r(r.x);
    hp[qposf(d4 + 1)] = tf32r(r.y);
    hp[qposf(d4 + 2)] = tf32r(r.z);
    hp[qposf(d4 + 3)] = tf32r(r.w);
}

// ---------------------------------------------------------------------------
// TF32 MMA GEMM, cp.async 3-stage, quad-K smem layout (LDS.128 fragments).
// A gmem: [M][K] quad-K; Bt gmem: [N][K] quad-K. C row-major (or quad if QOUT).
// Stage: A 4096 floats + B 4096 floats. Granule (16B) address:
//   (g*4+j)*128 + (row ^ 2j ^ 4g), g=k16 half, j=lane lt
// 128x128 tile, BK=32, 256 threads = 8 warps (4m x 2n), warp tile 32x64.
// ---------------------------------------------------------------------------
#define STG 3
#define STAGE_FLOATS 8192
#define GEMM_SMEM (STG*STAGE_FLOATS*4)   // 96 KB

template<bool RELU, bool RES, bool ROUND, bool QOUT>
__global__ void __launch_bounds__(256, 2) mma_gemm(
    const float* __restrict__ A, const float* __restrict__ Bt,
    const float* __restrict__ bias, const float* __restrict__ R,
    float* __restrict__ C, int M, int N, int K)
{
    extern __shared__ float smg[];
    uint32_t shBase = (uint32_t)__cvta_generic_to_shared(smg);

    const int tid  = threadIdx.x;
    const int lane = tid & 31;
    const int warp = tid >> 5;
    const int wm = (warp >> 1) * 32;
    const int wn = (warp & 1) * 64;
    const int bm = blockIdx.y * 128;
    const int bn = blockIdx.x * 128;
    const int lg = lane >> 2;
    const int lt = lane & 3;

    // Producer mapping
    const int pr = tid >> 1;          // row/col 0..127
    const int pg = tid & 1;           // k16 half
    const float* Ap = A  + (size_t)(bm + pr) * K + pg * 16;
    const float* Bp = Bt + (size_t)(bn + pr) * K + pg * 16;
    uint32_t aoff[4], boff[4];
    #pragma unroll
    for (int j = 0; j < 4; j++) {
        uint32_t gran = (uint32_t)((pg * 4 + j) * 128 + (pr ^ (2 * j) ^ (4 * pg)));
        aoff[j] = shBase + gran * 16;
        boff[j] = shBase + 4096 * 4 + gran * 16;
    }

    const int nk = K / 32;
    auto load_stage = [&](int it) {
        uint32_t off = (uint32_t)(it % STG) * (STAGE_FLOATS * 4);
        const float* ap = Ap + it * 32;
        const float* bp = Bp + it * 32;
        #pragma unroll
        for (int j = 0; j < 4; j++) cpa16(aoff[j] + off, ap + j * 4);
        #pragma unroll
        for (int j = 0; j < 4; j++) cpa16(boff[j] + off, bp + j * 4);
        cpa_commit();
    };

    float acc[2][8][4];
    #pragma unroll
    for (int mf = 0; mf < 2; mf++)
        #pragma unroll
        for (int nf = 0; nf < 8; nf++)
            #pragma unroll
            for (int i = 0; i < 4; i++) acc[mf][nf][i] = 0.f;

    const int e0 = lg ^ (2 * lt);

    load_stage(0);
    load_stage(1);

    for (int it = 0; it < nk; it++) {
        cpa_wait1();
        __syncthreads();
        if (it + 2 < nk) load_stage(it + 2);
        else cpa_commit();

        const float* as = smg + (it % STG) * STAGE_FLOATS;
        const float* bs = as + 4096;
        #pragma unroll
        for (int g = 0; g < 2; g++) {
            const int eg = e0 ^ (g << 2);
            const int gb = (g * 4 + lt) * 128;
            // A fragments for k8 steps ks0=g*16, ks1=g*16+8
            float ak0[2][4], ak1[2][4];
            #pragma unroll
            for (int mf = 0; mf < 2; mf++) {
                float4 t0 = *(const float4*)(as + ((gb + wm + mf * 16 + eg) << 2));
                float4 t1 = *(const float4*)(as + ((gb + wm + mf * 16 + 8 + eg) << 2));
                ak0[mf][0] = t0.x; ak0[mf][1] = t1.x;
                ak0[mf][2] = t0.y; ak0[mf][3] = t1.y;
                ak1[mf][0] = t0.z; ak1[mf][1] = t1.z;
                ak1[mf][2] = t0.w; ak1[mf][3] = t1.w;
            }
            #pragma unroll
            for (int nf = 0; nf < 8; nf++) {
                float4 bq = *(const float4*)(bs + ((gb + wn + nf * 8 + eg) << 2));
                float b0[2] = {bq.x, bq.y};
                float b1[2] = {bq.z, bq.w};
                mma_tf32(acc[0][nf], ak0[0], b0);
                mma_tf32(acc[1][nf], ak0[1], b0);
                mma_tf32(acc[0][nf], ak1[0], b1);
                mma_tf32(acc[1][nf], ak1[1], b1);
            }
        }
    }

    // Epilogue
    #pragma unroll
    for (int mf = 0; mf < 2; mf++) {
        int r0 = bm + wm + mf * 16 + lg;
        int r1 = r0 + 8;
        #pragma unroll
        for (int nf = 0; nf < 8; nf++) {
            int colRel = wn + nf * 8 + lt * 2;
            int col = bn + colRel;
            float2 bb = *(const float2*)(bias + col);
            float c0 = acc[mf][nf][0] + bb.x;
            float c1 = acc[mf][nf][1] + bb.y;
            float c2 = acc[mf][nf][2] + bb.x;
            float c3 = acc[mf][nf][3] + bb.y;
            if (RES) {
                float2 ra = *(const float2*)(R + (size_t)r0 * N + col);
                float2 rb = *(const float2*)(R + (size_t)r1 * N + col);
                c0 += ra.x; c1 += ra.y; c2 += rb.x; c3 += rb.y;
            }
            if (RELU) {
                c0 = fmaxf(c0, 0.f); c1 = fmaxf(c1, 0.f);
                c2 = fmaxf(c2, 0.f); c3 = fmaxf(c3, 0.f);
            }
            if (ROUND) {
                c0 = tf32r(c0); c1 = tf32r(c1); c2 = tf32r(c2); c3 = tf32r(c3);
            }
            if (QOUT) {
                int p0 = bn + qposf(colRel);
                int p1 = bn + qposf(colRel + 1);
                C[(size_t)r0 * N + p0] = c0;
                C[(size_t)r0 * N + p1] = c1;
                C[(size_t)r1 * N + p0] = c2;
                C[(size_t)r1 * N + p1] = c3;
            } else {
                *(float2*)(C + (size_t)r0 * N + col) = make_float2(c0, c1);
                *(float2*)(C + (size_t)r1 * N + col) = make_float2(c2, c3);
            }
        }
    }
}

// ---------------------------------------------------------------------------
// TF32 MMA flash attention (math identical to passing version; output now
// written in quad-K layout since it feeds the Wo GEMM)
// ---------------------------------------------------------------------------
#define KSTR 68
#define VSTR 72
#define ATTN_SMEM ((2*64*KSTR + 2*64*VSTR)*4)

__global__ void __launch_bounds__(128, 3) attn_mma(
    const float* __restrict__ qkv, float* __restrict__ O)
{
    extern __shared__ float sma[];
    float* sKhi = sma;
    float* sKlo = sKhi + 64 * KSTR;
    float* sVhi = sKlo + 64 * KSTR;
    float* sVlo = sVhi + 64 * VSTR;
    float* sP   = sKhi;

    const int tid  = threadIdx.x;
    const int lane = tid & 31;
    const int warp = tid >> 5;
    const int lg = lane >> 2;
    const int lt = lane & 3;
    const int wm = warp * 16;
    const int qb = blockIdx.x, h = blockIdx.y, b = blockIdx.z;

    const float* Qb = qkv + ((size_t)(b * NS + qb * 64)) * 1536 + h * 64;
    const float* Kb = qkv + ((size_t)b * NS) * 1536 + 512 + h * 64;
    const float* Vb = Kb + 512;

    const int r0 = wm + lg;
    const int r1 = r0 + 8;

    float qhi[8][4], qlo[8][4];
    #pragma unroll
    for (int ks = 0; ks < 8; ks++) {
        int c0 = ks * 8 + lt, c1 = c0 + 4;
        float v;
        v = Qb[(size_t)r0 * 1536 + c0]; qhi[ks][0] = tf32r(v); qlo[ks][0] = tf32r(v - qhi[ks][0]);
        v = Qb[(size_t)r1 * 1536 + c0]; qhi[ks][1] = tf32r(v); qlo[ks][1] = tf32r(v - qhi[ks][1]);
        v = Qb[(size_t)r0 * 1536 + c1]; qhi[ks][2] = tf32r(v); qlo[ks][2] = tf32r(v - qhi[ks][2]);
        v = Qb[(size_t)r1 * 1536 + c1]; qhi[ks][3] = tf32r(v); qlo[ks][3] = tf32r(v - qhi[ks][3]);
    }

    float m0 = -1e30f, m1 = -1e30f, l0 = 0.f, l1 = 0.f;
    float oA[8][4];
    #pragma unroll
    for (int nf = 0; nf < 8; nf++)
        oA[nf][0] = oA[nf][1] = oA[nf][2] = oA[nf][3] = 0.f;

    const int i0 = qb * 64 + r0;
    const int i1 = i0 + 8;

    const int t0 = (qb == (NS / 64 - 1)) ? 0 : qb;
    for (int t = t0; t < NS / 64; t++) {
        {
            int r  = tid >> 1;
            int cb = (tid & 1) * 32;
            const float* kp = Kb + (size_t)(t * 64 + r) * 1536 + cb;
            const float* vp = Vb + (size_t)(t * 64 + r) * 1536 + cb;
            #pragma unroll
            for (int i = 0; i < 8; i++) {
                float4 kv = *(const float4*)(kp + i * 4);
                float4 hi, lo;
                hi.x = tf32r(kv.x); lo.x = tf32r(kv.x - hi.x);
                hi.y = tf32r(kv.y); lo.y = tf32r(kv.y - hi.y);
                hi.z = tf32r(kv.z); lo.z = tf32r(kv.z - hi.z);
                hi.w = tf32r(kv.w); lo.w = tf32r(kv.w - hi.w);
                *(float4*)&sKhi[r * KSTR + cb + i * 4] = hi;
                *(float4*)&sKlo[r * KSTR + cb + i * 4] = lo;
                float4 vv = *(const float4*)(vp + i * 4);
                hi.x = tf32r(vv.x); lo.x = tf32r(vv.x - hi.x);
                hi.y = tf32r(vv.y); lo.y = tf32r(vv.y - hi.y);
                hi.z = tf32r(vv.z); lo.z = tf32r(vv.z - hi.z);
                hi.w = tf32r(vv.w); lo.w = tf32r(vv.w - hi.w);
                *(float4*)&sVhi[r * VSTR + cb + i * 4] = hi;
                *(float4*)&sVlo[r * VSTR + cb + i * 4] = lo;
            }
        }
        __syncthreads();

        float s[8][4];
        #pragma unroll
        for (int nf = 0; nf < 8; nf++)
            s[nf][0] = s[nf][1] = s[nf][2] = s[nf][3] = 0.f;
        #pragma unroll
        for (int ks = 0; ks < 8; ks++) {
            #pragma unroll
            for (int nf = 0; nf < 8; nf++) {
                int n = nf * 8 + lg;
                float bh[2], bl[2];
                bh[0] = sKhi[n * KSTR + ks * 8 + lt];
                bh[1] = sKhi[n * KSTR + ks * 8 + lt + 4];
                bl[0] = sKlo[n * KSTR + ks * 8 + lt];
                bl[1] = sKlo[n * KSTR + ks * 8 + lt + 4];
                mma_tf32(s[nf], qhi[ks], bh);
                mma_tf32(s[nf], qhi[ks], bl);
                mma_tf32(s[nf], qlo[ks], bh);
            }
        }

        const bool diag = (t <= qb);
        #pragma unroll
        for (int nf = 0; nf < 8; nf++) {
            if (diag) {
                int j0 = t * 64 + nf * 8 + lt * 2;
                s[nf][0] = (j0     > i0) ? s[nf][0] * 0.125f : -1e9f;
                s[nf][1] = (j0 + 1 > i0) ? s[nf][1] * 0.125f : -1e9f;
                s[nf][2] = (j0     > i1) ? s[nf][2] * 0.125f : -1e9f;
                s[nf][3] = (j0 + 1 > i1) ? s[nf][3] * 0.125f : -1e9f;
            } else {
                s[nf][0] *= 0.125f; s[nf][1] *= 0.125f;
                s[nf][2] *= 0.125f; s[nf][3] *= 0.125f;
            }
        }
        float mx0 = -1e30f, mx1 = -1e30f;
        #pragma unroll
        for (int nf = 0; nf < 8; nf++) {
            mx0 = fmaxf(mx0, fmaxf(s[nf][0], s[nf][1]));
            mx1 = fmaxf(mx1, fmaxf(s[nf][2], s[nf][3]));
        }
        mx0 = fmaxf(mx0, __shfl_xor_sync(0xffffffffu, mx0, 1));
        mx0 = fmaxf(mx0, __shfl_xor_sync(0xffffffffu, mx0, 2));
        mx1 = fmaxf(mx1, __shfl_xor_sync(0xffffffffu, mx1, 1));
        mx1 = fmaxf(mx1, __shfl_xor_sync(0xffffffffu, mx1, 2));
        float mn0 = fmaxf(m0, mx0), mn1 = fmaxf(m1, mx1);
        float corr0 = __expf(m0 - mn0), corr1 = __expf(m1 - mn1);
        m0 = mn0; m1 = mn1;
        float ls0 = 0.f, ls1 = 0.f;
        #pragma unroll
        for (int nf = 0; nf < 8; nf++) {
            float p;
            p = __expf(s[nf][0] - mn0); s[nf][0] = p; ls0 += p;
            p = __expf(s[nf][1] - mn0); s[nf][1] = p; ls0 += p;
            p = __expf(s[nf][2] - mn1); s[nf][2] = p; ls1 += p;
            p = __expf(s[nf][3] - mn1); s[nf][3] = p; ls1 += p;
        }
        ls0 += __shfl_xor_sync(0xffffffffu, ls0, 1);
        ls0 += __shfl_xor_sync(0xffffffffu, ls0, 2);
        ls1 += __shfl_xor_sync(0xffffffffu, ls1, 1);
        ls1 += __shfl_xor_sync(0xffffffffu, ls1, 2);
        l0 = l0 * corr0 + ls0;
        l1 = l1 * corr1 + ls1;
        #pragma unroll
        for (int nf = 0; nf < 8; nf++) {
            oA[nf][0] *= corr0; oA[nf][1] *= corr0;
            oA[nf][2] *= corr1; oA[nf][3] *= corr1;
        }
        __syncthreads();

        #pragma unroll
        for (int nf = 0; nf < 8; nf++) {
            int jl = nf * 8 + lt * 2;
            sP[r0 * KSTR + jl]     = tf32r(s[nf][0]);
            sP[r0 * KSTR + jl + 1] = tf32r(s[nf][1]);
            sP[r1 * KSTR + jl]     = tf32r(s[nf][2]);
            sP[r1 * KSTR + jl + 1] = tf32r(s[nf][3]);
        }
        __syncthreads();

        #pragma unroll
        for (int ks = 0; ks < 8; ks++) {
            float pa[4];
            pa[0] = sP[r0 * KSTR + ks * 8 + lt];
            pa[1] = sP[r1 * KSTR + ks * 8 + lt];
            pa[2] = sP[r0 * KSTR + ks * 8 + lt + 4];
            pa[3] = sP[r1 * KSTR + ks * 8 + lt + 4];
            #pragma unroll
            for (int nf = 0; nf < 8; nf++) {
                int n = nf * 8 + lg;
                float bh[2], bl[2];
                bh[0] = sVhi[(ks * 8 + lt) * VSTR + n];
                bh[1] = sVhi[(ks * 8 + lt + 4) * VSTR + n];
                bl[0] = sVlo[(ks * 8 + lt) * VSTR + n];
                bl[1] = sVlo[(ks * 8 + lt + 4) * VSTR + n];
                mma_tf32(oA[nf], pa, bh);
                mma_tf32(oA[nf], pa, bl);
            }
        }
        __syncthreads();
    }

    // Normalize + write in quad-K layout (tf32-rounded; feeds Wo gemm)
    float inv0 = 1.0f / l0, inv1 = 1.0f / l1;
    float* Op = O + ((size_t)(b * NS + qb * 64)) * ND + h * 64;
    #pragma unroll
    for (int nf = 0; nf < 8; nf++) {
        int d = nf * 8 + lt * 2;
        int p0 = qposf(d), p1 = qposf(d + 1);
        Op[(size_t)r0 * ND + p0] = tf32r(oA[nf][0] * inv0);
        Op[(size_t)r0 * ND + p1] = tf32r(oA[nf][1] * inv0);
        Op[(size_t)r1 * ND + p0] = tf32r(oA[nf][2] * inv1);
        Op[(size_t)r1 * ND + p1] = tf32r(oA[nf][3] * inv1);
    }
}

// ---------------------------------------------------------------------------
// LayerNorm: writes fp32 row-major (residual) + tf32-rounded quad-K (gemm A)
// ---------------------------------------------------------------------------
__global__ void ln_kernel(const float* __restrict__ X, const float* __restrict__ gam,
                          const float* __restrict__ bet, float* __restrict__ Yf,
                          float* __restrict__ Yr)
{
    int row  = blockIdx.x * 4 + (threadIdx.x >> 5);
    int lane = threadIdx.x & 31;
    const float* x = X + (size_t)row * ND;
    float4 v[4];
    float sum = 0.f;
    #pragma unroll
    for (int i = 0; i < 4; i++) {
        v[i] = *(const float4*)(x + lane * 4 + i * 128);
        sum += v[i].x + v[i].y + v[i].z + v[i].w;
    }
    #pragma unroll
    for (int off = 16; off; off >>= 1) sum += __shfl_xor_sync(0xffffffffu, sum, off);
    float mu = sum * (1.0f / 512.0f);
    float vs = 0.f;
    #pragma unroll
    for (int i = 0; i < 4; i++) {
        float dx;
        dx = v[i].x - mu; vs += dx * dx;
        dx = v[i].y - mu; vs += dx * dx;
        dx = v[i].z - mu; vs += dx * dx;
        dx = v[i].w - mu; vs += dx * dx;
    }
    #pragma unroll
    for (int off = 16; off; off >>= 1) vs += __shfl_xor_sync(0xffffffffu, vs, off);
    float rstd = rsqrtf(vs * (1.0f / 512.0f) + 1e-5f);
    float* yf = Yf + (size_t)row * ND;
    float* yr = Yr + (size_t)row * ND;
    #pragma unroll
    for (int i = 0; i < 4; i++) {
        float4 g4 = *(const float4*)(gam + lane * 4 + i * 128);
        float4 b4 = *(const float4*)(bet + lane * 4 + i * 128);
        float4 r;
        r.x = (v[i].x - mu) * rstd * g4.x + b4.x;
        r.y = (v[i].y - mu) * rstd * g4.y + b4.y;
        r.z = (v[i].z - mu) * rstd * g4.z + b4.z;
        r.w = (v[i].w - mu) * rstd * g4.w + b4.w;
        *(float4*)(yf + lane * 4 + i * 128) = r;
        int f = lane * 4 + i * 128;
        yr[qposf(f + 0)] = tf32r(r.x);
        yr[qposf(f + 1)] = tf32r(r.y);
        yr[qposf(f + 2)] = tf32r(r.z);
        yr[qposf(f + 3)] = tf32r(r.w);
    }
}

// ---------------------------------------------------------------------------
// Host orchestration
// ---------------------------------------------------------------------------
extern "C" void kernel_launch(void* const* d_in, const int* in_sizes, int n_in,
                              void* d_out, int out_size)
{
    const int*   ids  = (const int*)  d_in[0];
    const float* emb  = (const float*)d_in[1];
    const float* pe   = (const float*)d_in[2];
    const float* Wq   = (const float*)d_in[3];
    const float* bq   = (const float*)d_in[4];
    const float* Wk   = (const float*)d_in[5];
    const float* bk   = (const float*)d_in[6];
    const float* Wv   = (const float*)d_in[7];
    const float* bv   = (const float*)d_in[8];
    const float* Wo   = (const float*)d_in[9];
    const float* bo   = (const float*)d_in[10];
    const float* g1   = (const float*)d_in[11];
    const float* be1  = (const float*)d_in[12];
    const float* W1   = (const float*)d_in[13];
    const float* b1   = (const float*)d_in[14];
    const float* W2   = (const float*)d_in[15];
    const float* b2   = (const float*)d_in[16];
    const float* g2   = (const float*)d_in[17];
    const float* be2  = (const float*)d_in[18];
    const float* Wout = (const float*)d_in[19];
    const float* bout = (const float*)d_in[20];
    float* out = (float*)d_out;

    float* scratch = nullptr;
    cudaGetSymbolAddress((void**)&scratch, g_scratch);
    float* h      = scratch;
    float* h_r    = h      + SZ_HD;
    float* o      = h_r    + SZ_HD;
    float* tp     = o      + SZ_HD;
    float* qkv    = tp     + SZ_HD;
    float* ff     = qkv    + SZ_QKV;
    float* Wqkv_t = ff     + SZ_FF;
    float* Wo_t   = Wqkv_t + SZ_WQKV;
    float* W1_t   = Wo_t   + SZ_WO;
    float* W2_t   = W1_t   + SZ_W1;
    float* Wout_t = W2_t   + SZ_W2;
    float* bqkv   = Wout_t + SZ_WOUT;

    static bool attr_done = false;
    if (!attr_done) {
        cudaFuncSetAttribute(mma_gemm<false, false, false, false>,
                             cudaFuncAttributeMaxDynamicSharedMemorySize, GEMM_SMEM);
        cudaFuncSetAttribute(mma_gemm<false, true, false, false>,
                             cudaFuncAttributeMaxDynamicSharedMemorySize, GEMM_SMEM);
        cudaFuncSetAttribute(mma_gemm<true, false, true, true>,
                             cudaFuncAttributeMaxDynamicSharedMemorySize, GEMM_SMEM);
        cudaFuncSetAttribute(attn_mma,
                             cudaFuncAttributeMaxDynamicSharedMemorySize, ATTN_SMEM);
        attr_done = true;
    }

    // Pre-pass: transposed quad-K tf32 weights
    dim3 tb32(32, 8);
    trans_qkv<<<dim3(16, 16, 18), tb32>>>(Wq, Wk, Wv, Wqkv_t);
    trans_gen<<<dim3(16, 16, 6), tb32>>>(Wo, Wo_t, 512, 512);
    trans_gen<<<dim3(64, 16, 6), tb32>>>(W1, W1_t, 512, 2048);
    trans_gen<<<dim3(16, 64, 6), tb32>>>(W2, W2_t, 2048, 512);
    trans_gen<<<dim3(16, 16, 1), tb32>>>(Wout, Wout_t, 512, 512);
    pack_qkv_b<<<(int)(SZ_BQKV / 256), 256>>>(bq, bk, bv, bqkv);
    embed_kernel<<<(NM * ND / 4) / 256, 256>>>(ids, emb, pe, h, h_r);

    dim3 gQKV(1536 / 128, NM / 128);
    dim3 gP  (ND   / 128, NM / 128);
    dim3 gF1 (NF   / 128, NM / 128);
    dim3 attG(NS / 64, NH, NB);

    for (int L = 0; L < NL; L++) {
        size_t b_ = (size_t)L * ND;
        mma_gemm<false, false, false, false><<<gQKV, 256, GEMM_SMEM>>>(
            h_r, Wqkv_t + (size_t)L * 786432, bqkv + (size_t)L * 1536,
            nullptr, qkv, NM, 1536, ND);
        attn_mma<<<attG, 128, ATTN_SMEM>>>(qkv, o);
        mma_gemm<false, true, false, false><<<gP, 256, GEMM_SMEM>>>(
            o, Wo_t + (size_t)L * 262144, bo + b_, h, tp, NM, ND, ND);
        ln_kernel<<<NM / 4, 128>>>(tp, g1 + b_, be1 + b_, h, h_r);
        mma_gemm<true, false, true, true><<<gF1, 256, GEMM_SMEM>>>(
            h_r, W1_t + (size_t)L * 1048576, b1 + (size_t)L * NF,
            nullptr, ff, NM, NF, ND);
        mma_gemm<false, true, false, false><<<gP, 256, GEMM_SMEM>>>(
            ff, W2_t + (size_t)L * 1048576, b2 + b_, h, tp, NM, ND, NF);
        ln_kernel<<<NM / 4, 128>>>(tp, g2 + b_, be2 + b_, h, h_r);
    }
    mma_gemm<false, false, false, false><<<dim3(NV / 128, NM / 128), 256, GEMM_SMEM>>>(
        h_r, Wout_t, bout, nullptr, out, NM, NV, ND);
}

// round 14
// speedup vs baseline: 1.0535x; 1.0535x over previous
#include <cuda_runtime.h>
#include <math.h>
#include <stdint.h>

#define NB 8
#define NS 1024
#define ND 512
#define NH 8
#define NL 6
#define NF 2048
#define NV 512
#define NM (NB*NS)

#define SZ_HD   ((size_t)NM*ND)
#define SZ_QKV  ((size_t)NM*1536)
#define SZ_FF   ((size_t)NM*NF)
#define SZ_WQKV ((size_t)NL*512*1536)
#define SZ_WO   ((size_t)NL*512*512)
#define SZ_W1   ((size_t)NL*512*2048)
#define SZ_W2   ((size_t)NL*2048*512)
#define SZ_WOUT ((size_t)512*512)
#define SZ_BQKV ((size_t)NL*1536)
#define SZ_REST (SZ_WO + SZ_W1 + SZ_W2 + SZ_WOUT + SZ_BQKV)

__device__ float g_scratch[4*SZ_HD + SZ_QKV + SZ_FF + SZ_WQKV + SZ_REST];

__device__ __forceinline__ float tf32r(float x) {
    uint32_t y;
    asm("cvt.rna.tf32.f32 %0, %1;" : "=r"(y) : "f"(x));
    return __uint_as_float(y);
}

__device__ __forceinline__ void mma_tf32(float c[4], const float a[4],
                                         const float b[2]) {
    asm volatile(
        "mma.sync.aligned.m16n8k8.row.col.f32.tf32.tf32.f32 "
        "{%0,%1,%2,%3}, {%4,%5,%6,%7}, {%8,%9}, {%0,%1,%2,%3};\n"
        : "+f"(c[0]), "+f"(c[1]), "+f"(c[2]), "+f"(c[3])
        : "r"(__float_as_uint(a[0])), "r"(__float_as_uint(a[1])),
          "r"(__float_as_uint(a[2])), "r"(__float_as_uint(a[3])),
          "r"(__float_as_uint(b[0])), "r"(__float_as_uint(b[1])));
}

__device__ __forceinline__ void cpa16(uint32_t dst, const void* src) {
    asm volatile("cp.async.ca.shared.global [%0], [%1], 16;\n"
                 :: "r"(dst), "l"(src));
}
__device__ __forceinline__ void cpa_commit() {
    asm volatile("cp.async.commit_group;\n" ::);
}
__device__ __forceinline__ void cpa_wait1() {
    asm volatile("cp.async.wait_group 1;\n" ::);
}

// ---------------------------------------------------------------------------
// Pre-pass (2 launches) — round-11 layouts: Wqkv packed [K][N] row-major
// ---------------------------------------------------------------------------
__global__ void pack_qkv_w(const float* __restrict__ Wq, const float* __restrict__ Wk,
                           const float* __restrict__ Wv, float* __restrict__ dst) {
    size_t i = ((size_t)blockIdx.x * 256 + threadIdx.x);
    size_t e = i * 4;
    size_t l  = e / (512 * 1536);
    size_t r  = e % (512 * 1536);
    size_t k  = r / 1536;
    size_t j  = r % 1536;
    const float* src = (j < 512) ? Wq : (j < 1024) ? Wk : Wv;
    size_t jj = j & 511;
    float4 v = *(const float4*)(src + l * 262144 + k * 512 + jj);
    v.x = tf32r(v.x); v.y = tf32r(v.y); v.z = tf32r(v.z); v.w = tf32r(v.w);
    *(float4*)(dst + e) = v;
}

__global__ void round_rest(const float* __restrict__ Wo, const float* __restrict__ W1,
                           const float* __restrict__ W2, const float* __restrict__ Wout,
                           const float* __restrict__ bq, const float* __restrict__ bk,
                           const float* __restrict__ bv, float* __restrict__ dst) {
    size_t i4 = ((size_t)blockIdx.x * 256 + threadIdx.x) * 4;
    float4 v;
    bool rnd = true;
    if (i4 < SZ_WO) {
        v = *(const float4*)(Wo + i4);
    } else if (i4 < SZ_WO + SZ_W1) {
        v = *(const float4*)(W1 + (i4 - SZ_WO));
    } else if (i4 < SZ_WO + SZ_W1 + SZ_W2) {
        v = *(const float4*)(W2 + (i4 - SZ_WO - SZ_W1));
    } else if (i4 < SZ_WO + SZ_W1 + SZ_W2 + SZ_WOUT) {
        v = *(const float4*)(Wout + (i4 - SZ_WO - SZ_W1 - SZ_W2));
    } else {
        size_t e = i4 - (SZ_WO + SZ_W1 + SZ_W2 + SZ_WOUT);
        int l = (int)(e / 1536);
        int j = (int)(e % 1536);
        const float* src = (j < 512) ? bq : (j < 1024) ? bk : bv;
        v = *(const float4*)(src + l * 512 + (j & 511));
        rnd = false;
    }
    if (rnd) {
        v.x = tf32r(v.x); v.y = tf32r(v.y); v.z = tf32r(v.z); v.w = tf32r(v.w);
    }
    *(float4*)(dst + i4) = v;
}

// ---------------------------------------------------------------------------
// Embedding
// ---------------------------------------------------------------------------
__global__ void embed_kernel(const int* __restrict__ ids,
                             const float* __restrict__ emb,
                             const float* __restrict__ pe,
                             float* __restrict__ h, float* __restrict__ hr)
{
    int i = blockIdx.x * blockDim.x + threadIdx.x;
    int row = i >> 7;
    int d4  = (i & 127) << 2;
    int s   = row & (NS - 1);
    int tok = ids[row];
    const float SC = 22.62741699796952f;
    float4 e = *(const float4*)(emb + (size_t)tok * ND + d4);
    float4 p = *(const float4*)(pe  + (size_t)s   * ND + d4);
    float4 r;
    r.x = e.x * SC + p.x; r.y = e.y * SC + p.y;
    r.z = e.z * SC + p.z; r.w = e.w * SC + p.w;
    *(float4*)(h + (size_t)row * ND + d4) = r;
    float4 rr = make_float4(tf32r(r.x), tf32r(r.y), tf32r(r.z), tf32r(r.w));
    *(float4*)(hr + (size_t)row * ND + d4) = rr;
}

// ---------------------------------------------------------------------------
// TF32 MMA GEMM, cp.async 3-stage, XOR-swizzled conflict-free smem.
// Round-14 change: 512 threads = 16 warps, warp tile 32x32 (4m x 4n).
// acc 32 regs/thread -> __launch_bounds__(512, 2) = 32 warps/SM.
// A stage [128][32]: element(m,k) @ m*32 + ((k>>2)^(m&7))*4 + (k&3)
// B stage [32][128]: element(k,n) @ k*128 + ((n>>2)^(2*(k&3)))*4 + (n&3)
// ---------------------------------------------------------------------------
#define BKG 32
#define AST 4096
#define BST 4096
#define STG 3
#define GEMM_SMEM ((AST+BST)*STG*4)   // 96 KB

template<bool RELU, bool RES, bool ROUND>
__global__ void __launch_bounds__(512, 2) mma_gemm(
    const float* __restrict__ A, const float* __restrict__ W,
    const float* __restrict__ bias, const float* __restrict__ R,
    float* __restrict__ C, int M, int N, int K)
{
    extern __shared__ float smg[];
    float* As = smg;
    float* Bs = smg + STG * AST;
    uint32_t aSh = (uint32_t)__cvta_generic_to_shared(As);
    uint32_t bSh = (uint32_t)__cvta_generic_to_shared(Bs);

    const int tid  = threadIdx.x;
    const int lane = tid & 31;
    const int warp = tid >> 5;               // 0..15
    const int wm = (warp >> 2) * 32;         // 4 m-groups
    const int wn = (warp & 3) * 32;          // 4 n-groups
    const int bm = blockIdx.y * 128;
    const int bn = blockIdx.x * 128;
    const int lg = lane >> 2;
    const int lt = lane & 3;

    // Producer mapping (512 threads): A row 0..127 x quarter, B krow 0..31 x 16
    const int s_ar = tid >> 2;               // A row
    const int s_aq = tid & 3;                // chunk pair base (chunks 2q, 2q+1)
    const int s_br = tid >> 4;               // B k-row
    const int s_bc = tid & 15;               // chunks s_bc, s_bc+16

    const float* Ap = A + (size_t)(bm + s_ar) * K + s_aq * 8;
    const float* Wp = W + (size_t)s_br * N + bn + s_bc * 4;

    uint32_t aoff[2], boff[2];
    #pragma unroll
    for (int i = 0; i < 2; i++) {
        int pa = (s_aq * 2 + i) ^ (s_ar & 7);
        aoff[i] = aSh + (uint32_t)(s_ar * 32 + pa * 4) * 4;
        int pb = (s_bc + 16 * i) ^ ((s_br & 3) << 1);
        boff[i] = bSh + (uint32_t)(s_br * 128 + pb * 4) * 4;
    }

    const int nk = K / BKG;

    auto load_stage = [&](int it) {
        int s = it % STG;
        const float* ap = Ap + it * BKG;
        const float* wp = Wp + (size_t)it * BKG * N;
        uint32_t ab = (uint32_t)(s * AST) * 4;
        uint32_t bb = (uint32_t)(s * BST) * 4;
        cpa16(aoff[0] + ab, ap);
        cpa16(aoff[1] + ab, ap + 4);
        cpa16(boff[0] + bb, wp);
        cpa16(boff[1] + bb, wp + 64);
        cpa_commit();
    };

    float acc[2][4][4];
    #pragma unroll
    for (int mf = 0; mf < 2; mf++)
        #pragma unroll
        for (int nf = 0; nf < 4; nf++)
            #pragma unroll
            for (int i = 0; i < 4; i++) acc[mf][nf][i] = 0.f;

    const int arow_rd = (wm + lg) * 32 + lt;
    int brd[4];
    #pragma unroll
    for (int nf = 0; nf < 4; nf++) {
        int pb = (((wn >> 2) + 2 * nf + (lg >> 2)) ^ (2 * lt));
        brd[nf] = pb * 4 + (lg & 3) + lt * 128;
    }

    load_stage(0);
    load_stage(1);

    for (int it = 0; it < nk; it++) {
        cpa_wait1();
        __syncthreads();
        if (it + 2 < nk) load_stage(it + 2);
        else cpa_commit();

        const float* as = As + (it % STG) * AST;
        const float* bs = Bs + (it % STG) * BST;
        #pragma unroll
        for (int ks = 0; ks < 4; ks++) {
            const int x0 = ((2 * ks) ^ lg) * 4;
            const int x1 = ((2 * ks + 1) ^ lg) * 4;
            float af[2][4];
            #pragma unroll
            for (int mf = 0; mf < 2; mf++) {
                const float* a0 = as + arow_rd + mf * 512;
                af[mf][0] = a0[x0];
                af[mf][1] = a0[256 + x0];
                af[mf][2] = a0[x1];
                af[mf][3] = a0[256 + x1];
            }
            #pragma unroll
            for (int nf = 0; nf < 4; nf++) {
                const float* b0 = bs + ks * 1024 + brd[nf];
                float bf[2];
                bf[0] = b0[0];
                bf[1] = b0[512];
                mma_tf32(acc[0][nf], af[0], bf);
                mma_tf32(acc[1][nf], af[1], bf);
            }
        }
    }

    #pragma unroll
    for (int mf = 0; mf < 2; mf++) {
        int r0 = bm + wm + mf * 16 + lg;
        int r1 = r0 + 8;
        #pragma unroll
        for (int nf = 0; nf < 4; nf++) {
            int col = bn + wn + nf * 8 + lt * 2;
            float2 bb = *(const float2*)(bias + col);
            float c0 = acc[mf][nf][0] + bb.x;
            float c1 = acc[mf][nf][1] + bb.y;
            float c2 = acc[mf][nf][2] + bb.x;
            float c3 = acc[mf][nf][3] + bb.y;
            if (RES) {
                float2 ra = *(const float2*)(R + (size_t)r0 * N + col);
                float2 rb = *(const float2*)(R + (size_t)r1 * N + col);
                c0 += ra.x; c1 += ra.y; c2 += rb.x; c3 += rb.y;
            }
            if (RELU) {
                c0 = fmaxf(c0, 0.f); c1 = fmaxf(c1, 0.f);
                c2 = fmaxf(c2, 0.f); c3 = fmaxf(c3, 0.f);
            }
            if (ROUND) {
                c0 = tf32r(c0); c1 = tf32r(c1); c2 = tf32r(c2); c3 = tf32r(c3);
            }
            *(float2*)(C + (size_t)r0 * N + col) = make_float2(c0, c1);
            *(float2*)(C + (size_t)r1 * N + col) = make_float2(c2, c3);
        }
    }
}

// ---------------------------------------------------------------------------
// TF32 MMA flash attention (round-11 passing version, unchanged)
// ---------------------------------------------------------------------------
#define KSTR 68
#define VSTR 72
#define ATTN_SMEM ((2*64*KSTR + 2*64*VSTR)*4)

__global__ void __launch_bounds__(128, 3) attn_mma(
    const float* __restrict__ qkv, float* __restrict__ O)
{
    extern __shared__ float sma[];
    float* sKhi = sma;
    float* sKlo = sKhi + 64 * KSTR;
    float* sVhi = sKlo + 64 * KSTR;
    float* sVlo = sVhi + 64 * VSTR;
    float* sP   = sKhi;

    const int tid  = threadIdx.x;
    const int lane = tid & 31;
    const int warp = tid >> 5;
    const int lg = lane >> 2;
    const int lt = lane & 3;
    const int wm = warp * 16;
    const int qb = blockIdx.x, h = blockIdx.y, b = blockIdx.z;

    const float* Qb = qkv + ((size_t)(b * NS + qb * 64)) * 1536 + h * 64;
    const float* Kb = qkv + ((size_t)b * NS) * 1536 + 512 + h * 64;
    const float* Vb = Kb + 512;

    const int r0 = wm + lg;
    const int r1 = r0 + 8;

    float qhi[8][4], qlo[8][4];
    #pragma unroll
    for (int ks = 0; ks < 8; ks++) {
        int c0 = ks * 8 + lt, c1 = c0 + 4;
        float v;
        v = Qb[(size_t)r0 * 1536 + c0]; qhi[ks][0] = tf32r(v); qlo[ks][0] = tf32r(v - qhi[ks][0]);
        v = Qb[(size_t)r1 * 1536 + c0]; qhi[ks][1] = tf32r(v); qlo[ks][1] = tf32r(v - qhi[ks][1]);
        v = Qb[(size_t)r0 * 1536 + c1]; qhi[ks][2] = tf32r(v); qlo[ks][2] = tf32r(v - qhi[ks][2]);
        v = Qb[(size_t)r1 * 1536 + c1]; qhi[ks][3] = tf32r(v); qlo[ks][3] = tf32r(v - qhi[ks][3]);
    }

    float m0 = -1e30f, m1 = -1e30f, l0 = 0.f, l1 = 0.f;
    float oA[8][4];
    #pragma unroll
    for (int nf = 0; nf < 8; nf++)
        oA[nf][0] = oA[nf][1] = oA[nf][2] = oA[nf][3] = 0.f;

    const int i0 = qb * 64 + r0;
    const int i1 = i0 + 8;

    const int t0 = (qb == (NS / 64 - 1)) ? 0 : qb;
    for (int t = t0; t < NS / 64; t++) {
        {
            int r  = tid >> 1;
            int cb = (tid & 1) * 32;
            const float* kp = Kb + (size_t)(t * 64 + r) * 1536 + cb;
            const float* vp = Vb + (size_t)(t * 64 + r) * 1536 + cb;
            #pragma unroll
            for (int i = 0; i < 8; i++) {
                float4 kv = *(const float4*)(kp + i * 4);
                float4 hi, lo;
                hi.x = tf32r(kv.x); lo.x = tf32r(kv.x - hi.x);
                hi.y = tf32r(kv.y); lo.y = tf32r(kv.y - hi.y);
                hi.z = tf32r(kv.z); lo.z = tf32r(kv.z - hi.z);
                hi.w = tf32r(kv.w); lo.w = tf32r(kv.w - hi.w);
                *(float4*)&sKhi[r * KSTR + cb + i * 4] = hi;
                *(float4*)&sKlo[r * KSTR + cb + i * 4] = lo;
                float4 vv = *(const float4*)(vp + i * 4);
                hi.x = tf32r(vv.x); lo.x = tf32r(vv.x - hi.x);
                hi.y = tf32r(vv.y); lo.y = tf32r(vv.y - hi.y);
                hi.z = tf32r(vv.z); lo.z = tf32r(vv.z - hi.z);
                hi.w = tf32r(vv.w); lo.w = tf32r(vv.w - hi.w);
                *(float4*)&sVhi[r * VSTR + cb + i * 4] = hi;
                *(float4*)&sVlo[r * VSTR + cb + i * 4] = lo;
            }
        }
        __syncthreads();

        float s[8][4];
        #pragma unroll
        for (int nf = 0; nf < 8; nf++)
            s[nf][0] = s[nf][1] = s[nf][2] = s[nf][3] = 0.f;
        #pragma unroll
        for (int ks = 0; ks < 8; ks++) {
            #pragma unroll
            for (int nf = 0; nf < 8; nf++) {
                int n = nf * 8 + lg;
                float bh[2], bl[2];
                bh[0] = sKhi[n * KSTR + ks * 8 + lt];
                bh[1] = sKhi[n * KSTR + ks * 8 + lt + 4];
                bl[0] = sKlo[n * KSTR + ks * 8 + lt];
                bl[1] = sKlo[n * KSTR + ks * 8 + lt + 4];
                mma_tf32(s[nf], qhi[ks], bh);
                mma_tf32(s[nf], qhi[ks], bl);
                mma_tf32(s[nf], qlo[ks], bh);
            }
        }

        const bool diag = (t <= qb);
        #pragma unroll
        for (int nf = 0; nf < 8; nf++) {
            if (diag) {
                int j0 = t * 64 + nf * 8 + lt * 2;
                s[nf][0] = (j0     > i0) ? s[nf][0] * 0.125f : -1e9f;
                s[nf][1] = (j0 + 1 > i0) ? s[nf][1] * 0.125f : -1e9f;
                s[nf][2] = (j0     > i1) ? s[nf][2] * 0.125f : -1e9f;
                s[nf][3] = (j0 + 1 > i1) ? s[nf][3] * 0.125f : -1e9f;
            } else {
                s[nf][0] *= 0.125f; s[nf][1] *= 0.125f;
                s[nf][2] *= 0.125f; s[nf][3] *= 0.125f;
            }
        }
        float mx0 = -1e30f, mx1 = -1e30f;
        #pragma unroll
        for (int nf = 0; nf < 8; nf++) {
            mx0 = fmaxf(mx0, fmaxf(s[nf][0], s[nf][1]));
            mx1 = fmaxf(mx1, fmaxf(s[nf][2], s[nf][3]));
        }
        mx0 = fmaxf(mx0, __shfl_xor_sync(0xffffffffu, mx0, 1));
        mx0 = fmaxf(mx0, __shfl_xor_sync(0xffffffffu, mx0, 2));
        mx1 = fmaxf(mx1, __shfl_xor_sync(0xffffffffu, mx1, 1));
        mx1 = fmaxf(mx1, __shfl_xor_sync(0xffffffffu, mx1, 2));
        float mn0 = fmaxf(m0, mx0), mn1 = fmaxf(m1, mx1);
        float corr0 = __expf(m0 - mn0), corr1 = __expf(m1 - mn1);
        m0 = mn0; m1 = mn1;
        float ls0 = 0.f, ls1 = 0.f;
        #pragma unroll
        for (int nf = 0; nf < 8; nf++) {
            float p;
            p = __expf(s[nf][0] - mn0); s[nf][0] = p; ls0 += p;
            p = __expf(s[nf][1] - mn0); s[nf][1] = p; ls0 += p;
            p = __expf(s[nf][2] - mn1); s[nf][2] = p; ls1 += p;
            p = __expf(s[nf][3] - mn1); s[nf][3] = p; ls1 += p;
        }
        ls0 += __shfl_xor_sync(0xffffffffu, ls0, 1);
        ls0 += __shfl_xor_sync(0xffffffffu, ls0, 2);
        ls1 += __shfl_xor_sync(0xffffffffu, ls1, 1);
        ls1 += __shfl_xor_sync(0xffffffffu, ls1, 2);
        l0 = l0 * corr0 + ls0;
        l1 = l1 * corr1 + ls1;
        #pragma unroll
        for (int nf = 0; nf < 8; nf++) {
            oA[nf][0] *= corr0; oA[nf][1] *= corr0;
            oA[nf][2] *= corr1; oA[nf][3] *= corr1;
        }
        __syncthreads();

        #pragma unroll
        for (int nf = 0; nf < 8; nf++) {
            int jl = nf * 8 + lt * 2;
            sP[r0 * KSTR + jl]     = tf32r(s[nf][0]);
            sP[r0 * KSTR + jl + 1] = tf32r(s[nf][1]);
            sP[r1 * KSTR + jl]     = tf32r(s[nf][2]);
            sP[r1 * KSTR + jl + 1] = tf32r(s[nf][3]);
        }
        __syncthreads();

        #pragma unroll
        for (int ks = 0; ks < 8; ks++) {
            float pa[4];
            pa[0] = sP[r0 * KSTR + ks * 8 + lt];
            pa[1] = sP[r1 * KSTR + ks * 8 + lt];
            pa[2] = sP[r0 * KSTR + ks * 8 + lt + 4];
            pa[3] = sP[r1 * KSTR + ks * 8 + lt + 4];
            #pragma unroll
            for (int nf = 0; nf < 8; nf++) {
                int n = nf * 8 + lg;
                float bh[2], bl[2];
                bh[0] = sVhi[(ks * 8 + lt) * VSTR + n];
                bh[1] = sVhi[(ks * 8 + lt + 4) * VSTR + n];
                bl[0] = sVlo[(ks * 8 + lt) * VSTR + n];
                bl[1] = sVlo[(ks * 8 + lt + 4) * VSTR + n];
                mma_tf32(oA[nf], pa, bh);
                mma_tf32(oA[nf], pa, bl);
            }
        }
        __syncthreads();
    }

    float inv0 = 1.0f / l0, inv1 = 1.0f / l1;
    float* Op = O + ((size_t)(b * NS + qb * 64)) * ND + h * 64;
    #pragma unroll
    for (int nf = 0; nf < 8; nf++) {
        int d = nf * 8 + lt * 2;
        *(float2*)(Op + (size_t)r0 * ND + d) =
            make_float2(tf32r(oA[nf][0] * inv0), tf32r(oA[nf][1] * inv0));
        *(float2*)(Op + (size_t)r1 * ND + d) =
            make_float2(tf32r(oA[nf][2] * inv1), tf32r(oA[nf][3] * inv1));
    }
}

// ---------------------------------------------------------------------------
// LayerNorm
// ---------------------------------------------------------------------------
__global__ void ln_kernel(const float* __restrict__ X, const float* __restrict__ gam,
                          const float* __restrict__ bet, float* __restrict__ Yf,
                          float* __restrict__ Yr)
{
    int row  = blockIdx.x * 4 + (threadIdx.x >> 5);
    int lane = threadIdx.x & 31;
    const float* x = X + (size_t)row * ND;
    float4 v[4];
    float sum = 0.f;
    #pragma unroll
    for (int i = 0; i < 4; i++) {
        v[i] = *(const float4*)(x + lane * 4 + i * 128);
        sum += v[i].x + v[i].y + v[i].z + v[i].w;
    }
    #pragma unroll
    for (int off = 16; off; off >>= 1) sum += __shfl_xor_sync(0xffffffffu, sum, off);
    float mu = sum * (1.0f / 512.0f);
    float vs = 0.f;
    #pragma unroll
    for (int i = 0; i < 4; i++) {
        float dx;
        dx = v[i].x - mu; vs += dx * dx;
        dx = v[i].y - mu; vs += dx * dx;
        dx = v[i].z - mu; vs += dx * dx;
        dx = v[i].w - mu; vs += dx * dx;
    }
    #pragma unroll
    for (int off = 16; off; off >>= 1) vs += __shfl_xor_sync(0xffffffffu, vs, off);
    float rstd = rsqrtf(vs * (1.0f / 512.0f) + 1e-5f);
    float* yf = Yf + (size_t)row * ND;
    float* yr = Yr + (size_t)row * ND;
    #pragma unroll
    for (int i = 0; i < 4; i++) {
        float4 g4 = *(const float4*)(gam + lane * 4 + i * 128);
        float4 b4 = *(const float4*)(bet + lane * 4 + i * 128);
        float4 r;
        r.x = (v[i].x - mu) * rstd * g4.x + b4.x;
        r.y = (v[i].y - mu) * rstd * g4.y + b4.y;
        r.z = (v[i].z - mu) * rstd * g4.z + b4.z;
        r.w = (v[i].w - mu) * rstd * g4.w + b4.w;
        *(float4*)(yf + lane * 4 + i * 128) = r;
        float4 rr = make_float4(tf32r(r.x), tf32r(r.y), tf32r(r.z), tf32r(r.w));
        *(float4*)(yr + lane * 4 + i * 128) = rr;
    }
}

// ---------------------------------------------------------------------------
// Host orchestration
// ---------------------------------------------------------------------------
extern "C" void kernel_launch(void* const* d_in, const int* in_sizes, int n_in,
                              void* d_out, int out_size)
{
    const int*   ids  = (const int*)  d_in[0];
    const float* emb  = (const float*)d_in[1];
    const float* pe   = (const float*)d_in[2];
    const float* Wq   = (const float*)d_in[3];
    const float* bq   = (const float*)d_in[4];
    const float* Wk   = (const float*)d_in[5];
    const float* bk   = (const float*)d_in[6];
    const float* Wv   = (const float*)d_in[7];
    const float* bv   = (const float*)d_in[8];
    const float* Wo   = (const float*)d_in[9];
    const float* bo   = (const float*)d_in[10];
    const float* g1   = (const float*)d_in[11];
    const float* be1  = (const float*)d_in[12];
    const float* W1   = (const float*)d_in[13];
    const float* b1   = (const float*)d_in[14];
    const float* W2   = (const float*)d_in[15];
    const float* b2   = (const float*)d_in[16];
    const float* g2   = (const float*)d_in[17];
    const float* be2  = (const float*)d_in[18];
    const float* Wout = (const float*)d_in[19];
    const float* bout = (const float*)d_in[20];
    float* out = (float*)d_out;

    float* scratch = nullptr;
    cudaGetSymbolAddress((void**)&scratch, g_scratch);
    float* h      = scratch;
    float* h_r    = h      + SZ_HD;
    float* o      = h_r    + SZ_HD;
    float* tp     = o      + SZ_HD;
    float* qkv    = tp     + SZ_HD;
    float* ff     = qkv    + SZ_QKV;
    float* Wqkv_r = ff     + SZ_FF;
    float* Wo_r   = Wqkv_r + SZ_WQKV;
    float* W1_r   = Wo_r   + SZ_WO;
    float* W2_r   = W1_r   + SZ_W1;
    float* Wout_r = W2_r   + SZ_W2;
    float* bqkv   = Wout_r + SZ_WOUT;

    static bool attr_done = false;
    if (!attr_done) {
        cudaFuncSetAttribute(mma_gemm<false, false, false>,
                             cudaFuncAttributeMaxDynamicSharedMemorySize, GEMM_SMEM);
        cudaFuncSetAttribute(mma_gemm<false, true, false>,
                             cudaFuncAttributeMaxDynamicSharedMemorySize, GEMM_SMEM);
        cudaFuncSetAttribute(mma_gemm<true, false, true>,
                             cudaFuncAttributeMaxDynamicSharedMemorySize, GEMM_SMEM);
        cudaFuncSetAttribute(attn_mma,
                             cudaFuncAttributeMaxDynamicSharedMemorySize, ATTN_SMEM);
        attr_done = true;
    }

    pack_qkv_w<<<(int)(SZ_WQKV / 4 / 256), 256>>>(Wq, Wk, Wv, Wqkv_r);
    round_rest<<<(int)(SZ_REST / 4 / 256), 256>>>(Wo, W1, W2, Wout, bq, bk, bv, Wo_r);
    embed_kernel<<<(NM * ND / 4) / 256, 256>>>(ids, emb, pe, h, h_r);

    dim3 gQKV(1536 / 128, NM / 128);
    dim3 gP  (ND   / 128, NM / 128);
    dim3 gF1 (NF   / 128, NM / 128);
    dim3 attG(NS / 64, NH, NB);

    for (int L = 0; L < NL; L++) {
        size_t b_ = (size_t)L * ND;
        mma_gemm<false, false, false><<<gQKV, 512, GEMM_SMEM>>>(
            h_r, Wqkv_r + (size_t)L * 786432, bqkv + (size_t)L * 1536,
            nullptr, qkv, NM, 1536, ND);
        attn_mma<<<attG, 128, ATTN_SMEM>>>(qkv, o);
        mma_gemm<false, true, false><<<gP, 512, GEMM_SMEM>>>(
            o, Wo_r + (size_t)L * 262144, bo + b_, h, tp, NM, ND, ND);
        ln_kernel<<<NM / 4, 128>>>(tp, g1 + b_, be1 + b_, h, h_r);
        mma_gemm<true, false, true><<<gF1, 512, GEMM_SMEM>>>(
            h_r, W1_r + (size_t)L * 1048576, b1 + (size_t)L * NF,
            nullptr, ff, NM, NF, ND);
        mma_gemm<false, true, false><<<gP, 512, GEMM_SMEM>>>(
            ff, W2_r + (size_t)L * 1048576, b2 + b_, h, tp, NM, ND, NF);
        ln_kernel<<<NM / 4, 128>>>(tp, g2 + b_, be2 + b_, h, h_r);
    }
    mma_gemm<false, false, false><<<dim3(NV / 128, NM / 128), 512, GEMM_SMEM>>>(
        h_r, Wout_r, bout, nullptr, out, NM, NV, ND);
}

// round 15
// speedup vs baseline: 1.2860x; 1.2207x over previous
#include <cuda_runtime.h>
#include <cuda_bf16.h>
#include <math.h>
#include <stdint.h>

#define NB 8
#define NS 1024
#define ND 512
#define NH 8
#define NL 6
#define NF 2048
#define NV 512
#define NM (NB*NS)

#define SZ_HD   ((size_t)NM*ND)
#define SZ_QKV  ((size_t)NM*1536)
#define SZ_FF   ((size_t)NM*NF)
#define SZ_WQKV ((size_t)NL*512*1536)
#define SZ_WO   ((size_t)NL*512*512)
#define SZ_W1   ((size_t)NL*512*2048)
#define SZ_W2   ((size_t)NL*2048*512)
#define SZ_WOUT ((size_t)512*512)
#define SZ_BQKV ((size_t)NL*1536)
#define SZ_REST (SZ_WO + SZ_W1 + SZ_W2 + SZ_WOUT + SZ_BQKV)

__device__ float g_scratch[4*SZ_HD + SZ_QKV + SZ_FF + SZ_WQKV + SZ_REST];

__device__ __forceinline__ float tf32r(float x) {
    uint32_t y;
    asm("cvt.rna.tf32.f32 %0, %1;" : "=r"(y) : "f"(x));
    return __uint_as_float(y);
}

__device__ __forceinline__ void mma_tf32(float c[4], const float a[4],
                                         const float b[2]) {
    asm volatile(
        "mma.sync.aligned.m16n8k8.row.col.f32.tf32.tf32.f32 "
        "{%0,%1,%2,%3}, {%4,%5,%6,%7}, {%8,%9}, {%0,%1,%2,%3};\n"
        : "+f"(c[0]), "+f"(c[1]), "+f"(c[2]), "+f"(c[3])
        : "r"(__float_as_uint(a[0])), "r"(__float_as_uint(a[1])),
          "r"(__float_as_uint(a[2])), "r"(__float_as_uint(a[3])),
          "r"(__float_as_uint(b[0])), "r"(__float_as_uint(b[1])));
}

__device__ __forceinline__ void mma_bf16(float c[4], const uint32_t a[4],
                                         const uint32_t b[2]) {
    asm volatile(
        "mma.sync.aligned.m16n8k16.row.col.f32.bf16.bf16.f32 "
        "{%0,%1,%2,%3}, {%4,%5,%6,%7}, {%8,%9}, {%0,%1,%2,%3};\n"
        : "+f"(c[0]), "+f"(c[1]), "+f"(c[2]), "+f"(c[3])
        : "r"(a[0]), "r"(a[1]), "r"(a[2]), "r"(a[3]),
          "r"(b[0]), "r"(b[1]));
}

// Split (x,y) into packed bf16 hi pair + bf16 lo (residual) pair. x -> low 16.
__device__ __forceinline__ void bsplit2(float x, float y, uint32_t& hi, uint32_t& lo) {
    __nv_bfloat162 h = __floats2bfloat162_rn(x, y);
    float hx = __bfloat162float(h.x);
    float hy = __bfloat162float(h.y);
    __nv_bfloat162 l = __floats2bfloat162_rn(x - hx, y - hy);
    hi = *reinterpret_cast<uint32_t*>(&h);
    lo = *reinterpret_cast<uint32_t*>(&l);
}

__device__ __forceinline__ void cpa16(uint32_t dst, const void* src) {
    asm volatile("cp.async.ca.shared.global [%0], [%1], 16;\n"
                 :: "r"(dst), "l"(src));
}
__device__ __forceinline__ void cpa_commit() {
    asm volatile("cp.async.commit_group;\n" ::);
}
__device__ __forceinline__ void cpa_wait1() {
    asm volatile("cp.async.wait_group 1;\n" ::);
}

// ---------------------------------------------------------------------------
// Pre-pass (2 launches)
// ---------------------------------------------------------------------------
__global__ void pack_qkv_w(const float* __restrict__ Wq, const float* __restrict__ Wk,
                           const float* __restrict__ Wv, float* __restrict__ dst) {
    size_t i = ((size_t)blockIdx.x * 256 + threadIdx.x);
    size_t e = i * 4;
    size_t l  = e / (512 * 1536);
    size_t r  = e % (512 * 1536);
    size_t k  = r / 1536;
    size_t j  = r % 1536;
    const float* src = (j < 512) ? Wq : (j < 1024) ? Wk : Wv;
    size_t jj = j & 511;
    float4 v = *(const float4*)(src + l * 262144 + k * 512 + jj);
    v.x = tf32r(v.x); v.y = tf32r(v.y); v.z = tf32r(v.z); v.w = tf32r(v.w);
    *(float4*)(dst + e) = v;
}

__global__ void round_rest(const float* __restrict__ Wo, const float* __restrict__ W1,
                           const float* __restrict__ W2, const float* __restrict__ Wout,
                           const float* __restrict__ bq, const float* __restrict__ bk,
                           const float* __restrict__ bv, float* __restrict__ dst) {
    size_t i4 = ((size_t)blockIdx.x * 256 + threadIdx.x) * 4;
    float4 v;
    bool rnd = true;
    if (i4 < SZ_WO) {
        v = *(const float4*)(Wo + i4);
    } else if (i4 < SZ_WO + SZ_W1) {
        v = *(const float4*)(W1 + (i4 - SZ_WO));
    } else if (i4 < SZ_WO + SZ_W1 + SZ_W2) {
        v = *(const float4*)(W2 + (i4 - SZ_WO - SZ_W1));
    } else if (i4 < SZ_WO + SZ_W1 + SZ_W2 + SZ_WOUT) {
        v = *(const float4*)(Wout + (i4 - SZ_WO - SZ_W1 - SZ_W2));
    } else {
        size_t e = i4 - (SZ_WO + SZ_W1 + SZ_W2 + SZ_WOUT);
        int l = (int)(e / 1536);
        int j = (int)(e % 1536);
        const float* src = (j < 512) ? bq : (j < 1024) ? bk : bv;
        v = *(const float4*)(src + l * 512 + (j & 511));
        rnd = false;
    }
    if (rnd) {
        v.x = tf32r(v.x); v.y = tf32r(v.y); v.z = tf32r(v.z); v.w = tf32r(v.w);
    }
    *(float4*)(dst + i4) = v;
}

// ---------------------------------------------------------------------------
// Embedding
// ---------------------------------------------------------------------------
__global__ void embed_kernel(const int* __restrict__ ids,
                             const float* __restrict__ emb,
                             const float* __restrict__ pe,
                             float* __restrict__ h, float* __restrict__ hr)
{
    int i = blockIdx.x * blockDim.x + threadIdx.x;
    int row = i >> 7;
    int d4  = (i & 127) << 2;
    int s   = row & (NS - 1);
    int tok = ids[row];
    const float SC = 22.62741699796952f;
    float4 e = *(const float4*)(emb + (size_t)tok * ND + d4);
    float4 p = *(const float4*)(pe  + (size_t)s   * ND + d4);
    float4 r;
    r.x = e.x * SC + p.x; r.y = e.y * SC + p.y;
    r.z = e.z * SC + p.z; r.w = e.w * SC + p.w;
    *(float4*)(h + (size_t)row * ND + d4) = r;
    float4 rr = make_float4(tf32r(r.x), tf32r(r.y), tf32r(r.z), tf32r(r.w));
    *(float4*)(hr + (size_t)row * ND + d4) = rr;
}

// ---------------------------------------------------------------------------
// TF32 MMA GEMM (round-14 version, unchanged: 512 thr, 16 warps 32x32,
// 3-stage cp.async, XOR-swizzled conflict-free smem)
// ---------------------------------------------------------------------------
#define BKG 32
#define AST 4096
#define BST 4096
#define STG 3
#define GEMM_SMEM ((AST+BST)*STG*4)   // 96 KB

template<bool RELU, bool RES, bool ROUND>
__global__ void __launch_bounds__(512, 2) mma_gemm(
    const float* __restrict__ A, const float* __restrict__ W,
    const float* __restrict__ bias, const float* __restrict__ R,
    float* __restrict__ C, int M, int N, int K)
{
    extern __shared__ float smg[];
    float* As = smg;
    float* Bs = smg + STG * AST;
    uint32_t aSh = (uint32_t)__cvta_generic_to_shared(As);
    uint32_t bSh = (uint32_t)__cvta_generic_to_shared(Bs);

    const int tid  = threadIdx.x;
    const int lane = tid & 31;
    const int warp = tid >> 5;
    const int wm = (warp >> 2) * 32;
    const int wn = (warp & 3) * 32;
    const int bm = blockIdx.y * 128;
    const int bn = blockIdx.x * 128;
    const int lg = lane >> 2;
    const int lt = lane & 3;

    const int s_ar = tid >> 2;
    const int s_aq = tid & 3;
    const int s_br = tid >> 4;
    const int s_bc = tid & 15;

    const float* Ap = A + (size_t)(bm + s_ar) * K + s_aq * 8;
    const float* Wp = W + (size_t)s_br * N + bn + s_bc * 4;

    uint32_t aoff[2], boff[2];
    #pragma unroll
    for (int i = 0; i < 2; i++) {
        int pa = (s_aq * 2 + i) ^ (s_ar & 7);
        aoff[i] = aSh + (uint32_t)(s_ar * 32 + pa * 4) * 4;
        int pb = (s_bc + 16 * i) ^ ((s_br & 3) << 1);
        boff[i] = bSh + (uint32_t)(s_br * 128 + pb * 4) * 4;
    }

    const int nk = K / BKG;

    auto load_stage = [&](int it) {
        int s = it % STG;
        const float* ap = Ap + it * BKG;
        const float* wp = Wp + (size_t)it * BKG * N;
        uint32_t ab = (uint32_t)(s * AST) * 4;
        uint32_t bb = (uint32_t)(s * BST) * 4;
        cpa16(aoff[0] + ab, ap);
        cpa16(aoff[1] + ab, ap + 4);
        cpa16(boff[0] + bb, wp);
        cpa16(boff[1] + bb, wp + 64);
        cpa_commit();
    };

    float acc[2][4][4];
    #pragma unroll
    for (int mf = 0; mf < 2; mf++)
        #pragma unroll
        for (int nf = 0; nf < 4; nf++)
            #pragma unroll
            for (int i = 0; i < 4; i++) acc[mf][nf][i] = 0.f;

    const int arow_rd = (wm + lg) * 32 + lt;
    int brd[4];
    #pragma unroll
    for (int nf = 0; nf < 4; nf++) {
        int pb = (((wn >> 2) + 2 * nf + (lg >> 2)) ^ (2 * lt));
        brd[nf] = pb * 4 + (lg & 3) + lt * 128;
    }

    load_stage(0);
    load_stage(1);

    for (int it = 0; it < nk; it++) {
        cpa_wait1();
        __syncthreads();
        if (it + 2 < nk) load_stage(it + 2);
        else cpa_commit();

        const float* as = As + (it % STG) * AST;
        const float* bs = Bs + (it % STG) * BST;
        #pragma unroll
        for (int ks = 0; ks < 4; ks++) {
            const int x0 = ((2 * ks) ^ lg) * 4;
            const int x1 = ((2 * ks + 1) ^ lg) * 4;
            float af[2][4];
            #pragma unroll
            for (int mf = 0; mf < 2; mf++) {
                const float* a0 = as + arow_rd + mf * 512;
                af[mf][0] = a0[x0];
                af[mf][1] = a0[256 + x0];
                af[mf][2] = a0[x1];
                af[mf][3] = a0[256 + x1];
            }
            #pragma unroll
            for (int nf = 0; nf < 4; nf++) {
                const float* b0 = bs + ks * 1024 + brd[nf];
                float bf[2];
                bf[0] = b0[0];
                bf[1] = b0[512];
                mma_tf32(acc[0][nf], af[0], bf);
                mma_tf32(acc[1][nf], af[1], bf);
            }
        }
    }

    #pragma unroll
    for (int mf = 0; mf < 2; mf++) {
        int r0 = bm + wm + mf * 16 + lg;
        int r1 = r0 + 8;
        #pragma unroll
        for (int nf = 0; nf < 4; nf++) {
            int col = bn + wn + nf * 8 + lt * 2;
            float2 bb = *(const float2*)(bias + col);
            float c0 = acc[mf][nf][0] + bb.x;
            float c1 = acc[mf][nf][1] + bb.y;
            float c2 = acc[mf][nf][2] + bb.x;
            float c3 = acc[mf][nf][3] + bb.y;
            if (RES) {
                float2 ra = *(const float2*)(R + (size_t)r0 * N + col);
                float2 rb = *(const float2*)(R + (size_t)r1 * N + col);
                c0 += ra.x; c1 += ra.y; c2 += rb.x; c3 += rb.y;
            }
            if (RELU) {
                c0 = fmaxf(c0, 0.f); c1 = fmaxf(c1, 0.f);
                c2 = fmaxf(c2, 0.f); c3 = fmaxf(c3, 0.f);
            }
            if (ROUND) {
                c0 = tf32r(c0); c1 = tf32r(c1); c2 = tf32r(c2); c3 = tf32r(c3);
            }
            *(float2*)(C + (size_t)r0 * N + col) = make_float2(c0, c1);
            *(float2*)(C + (size_t)r1 * N + col) = make_float2(c2, c3);
        }
    }
}

// ---------------------------------------------------------------------------
// bf16 (m16n8k16) flash attention with hi/lo compensation.
// Scores = Qhi*Khi + Qhi*Klo + Qlo*Khi; O += Phi*Vhi + Phi*Vlo + Plo*Vhi.
// P never touches smem: QK C-fragments match PV A-fragments directly.
// K tile: sK[kpos][dpair] u32 (bf16 pair along d), stride 36 (reads 4lg+lt
// conflict-free). V tile transposed: sVt[jpair][d] u32 (pair along j),
// stride 68 (reads 4lt+lg conflict-free, writes lane-d conflict-free).
// Mask semantics identical: keep strictly j > i, masked = -1e9, scale 0.125
// pre-mask, skip fully-masked tiles except for the last Q block.
// Output tf32-rounded (feeds Wo GEMM).
// ---------------------------------------------------------------------------
#define KPAD 36
#define VPAD 68
#define ATTN_SMEM ((2*64*KPAD + 2*32*VPAD)*4)   // 35840 B

__global__ void __launch_bounds__(128, 4) attn_mma(
    const float* __restrict__ qkv, float* __restrict__ O)
{
    extern __shared__ uint32_t smu[];
    uint32_t* sKhi = smu;                     // [64][KPAD]
    uint32_t* sKlo = sKhi + 64 * KPAD;
    uint32_t* sVhi = sKlo + 64 * KPAD;        // [32][VPAD]
    uint32_t* sVlo = sVhi + 32 * VPAD;

    const int tid  = threadIdx.x;
    const int lane = tid & 31;
    const int warp = tid >> 5;
    const int lg = lane >> 2;
    const int lt = lane & 3;
    const int wm = warp * 16;
    const int qb = blockIdx.x, h = blockIdx.y, b = blockIdx.z;

    const float* Qb = qkv + ((size_t)(b * NS + qb * 64)) * 1536 + h * 64;
    const float* Kb = qkv + ((size_t)b * NS) * 1536 + 512 + h * 64;
    const float* Vb = Kb + 512;

    const int r0 = wm + lg;
    const int r1 = r0 + 8;

    // Q fragments: 4 k16-chunks, packed bf16 hi/lo
    uint32_t qhi[4][4], qlo[4][4];
    #pragma unroll
    for (int c = 0; c < 4; c++) {
        int d0 = 16 * c + 2 * lt;
        int d1 = d0 + 8;
        float2 x00 = *(const float2*)(Qb + (size_t)r0 * 1536 + d0);
        float2 x10 = *(const float2*)(Qb + (size_t)r1 * 1536 + d0);
        float2 x01 = *(const float2*)(Qb + (size_t)r0 * 1536 + d1);
        float2 x11 = *(const float2*)(Qb + (size_t)r1 * 1536 + d1);
        bsplit2(x00.x, x00.y, qhi[c][0], qlo[c][0]);
        bsplit2(x10.x, x10.y, qhi[c][1], qlo[c][1]);
        bsplit2(x01.x, x01.y, qhi[c][2], qlo[c][2]);
        bsplit2(x11.x, x11.y, qhi[c][3], qlo[c][3]);
    }

    float m0 = -1e30f, m1 = -1e30f, l0 = 0.f, l1 = 0.f;
    float oA[8][4];
    #pragma unroll
    for (int nf = 0; nf < 8; nf++)
        oA[nf][0] = oA[nf][1] = oA[nf][2] = oA[nf][3] = 0.f;

    const int i0 = qb * 64 + r0;
    const int i1 = i0 + 8;

    const int t0 = (qb == (NS / 64 - 1)) ? 0 : qb;
    for (int t = t0; t < NS / 64; t++) {
        // ---- K tile: split hi/lo, pack pairs along d ----
        {
            int r     = tid >> 1;
            int halfb = tid & 1;
            const float* kp = Kb + (size_t)(t * 64 + r) * 1536 + halfb * 32;
            uint32_t* kh = sKhi + r * KPAD + halfb * 16;
            uint32_t* kl = sKlo + r * KPAD + halfb * 16;
            #pragma unroll
            for (int i = 0; i < 8; i++) {
                float4 v = *(const float4*)(kp + i * 4);
                uint32_t h0, lo0, h1, lo1;
                bsplit2(v.x, v.y, h0, lo0);
                bsplit2(v.z, v.w, h1, lo1);
                kh[i * 2]     = h0; kh[i * 2 + 1] = h1;
                kl[i * 2]     = lo0; kl[i * 2 + 1] = lo1;
            }
        }
        // ---- V tile: transpose-pack pairs along j ----
        {
            int w4 = tid >> 5;
            int d  = (tid & 31) * 2;
            #pragma unroll
            for (int i = 0; i < 8; i++) {
                int jp = i * 4 + w4;
                const float* vp = Vb + (size_t)(t * 64 + 2 * jp) * 1536 + d;
                float2 v0 = *(const float2*)(vp);
                float2 v1 = *(const float2*)(vp + 1536);
                uint32_t h0, lo0, h1, lo1;
                bsplit2(v0.x, v1.x, h0, lo0);   // column d
                bsplit2(v0.y, v1.y, h1, lo1);   // column d+1
                sVhi[jp * VPAD + d]     = h0;
                sVhi[jp * VPAD + d + 1] = h1;
                sVlo[jp * VPAD + d]     = lo0;
                sVlo[jp * VPAD + d + 1] = lo1;
            }
        }
        __syncthreads();

        // ---- Scores: Qhi*Khi + Qhi*Klo + Qlo*Khi ----
        float s[8][4];
        #pragma unroll
        for (int nf = 0; nf < 8; nf++)
            s[nf][0] = s[nf][1] = s[nf][2] = s[nf][3] = 0.f;
        #pragma unroll
        for (int c = 0; c < 4; c++) {
            #pragma unroll
            for (int nf = 0; nf < 8; nf++) {
                int rowb = (nf * 8 + lg) * KPAD;
                uint32_t bh[2], bl[2];
                bh[0] = sKhi[rowb + c * 8 + lt];
                bh[1] = sKhi[rowb + c * 8 + 4 + lt];
                bl[0] = sKlo[rowb + c * 8 + lt];
                bl[1] = sKlo[rowb + c * 8 + 4 + lt];
                mma_bf16(s[nf], qhi[c], bh);
                mma_bf16(s[nf], qhi[c], bl);
                mma_bf16(s[nf], qlo[c], bh);
            }
        }

        // ---- Mask + online softmax (identical semantics) ----
        const bool diag = (t <= qb);
        #pragma unroll
        for (int nf = 0; nf < 8; nf++) {
            if (diag) {
                int j0 = t * 64 + nf * 8 + lt * 2;
                s[nf][0] = (j0     > i0) ? s[nf][0] * 0.125f : -1e9f;
                s[nf][1] = (j0 + 1 > i0) ? s[nf][1] * 0.125f : -1e9f;
                s[nf][2] = (j0     > i1) ? s[nf][2] * 0.125f : -1e9f;
                s[nf][3] = (j0 + 1 > i1) ? s[nf][3] * 0.125f : -1e9f;
            } else {
                s[nf][0] *= 0.125f; s[nf][1] *= 0.125f;
                s[nf][2] *= 0.125f; s[nf][3] *= 0.125f;
            }
        }
        float mx0 = -1e30f, mx1 = -1e30f;
        #pragma unroll
        for (int nf = 0; nf < 8; nf++) {
            mx0 = fmaxf(mx0, fmaxf(s[nf][0], s[nf][1]));
            mx1 = fmaxf(mx1, fmaxf(s[nf][2], s[nf][3]));
        }
        mx0 = fmaxf(mx0, __shfl_xor_sync(0xffffffffu, mx0, 1));
        mx0 = fmaxf(mx0, __shfl_xor_sync(0xffffffffu, mx0, 2));
        mx1 = fmaxf(mx1, __shfl_xor_sync(0xffffffffu, mx1, 1));
        mx1 = fmaxf(mx1, __shfl_xor_sync(0xffffffffu, mx1, 2));
        float mn0 = fmaxf(m0, mx0), mn1 = fmaxf(m1, mx1);
        float corr0 = __expf(m0 - mn0), corr1 = __expf(m1 - mn1);
        m0 = mn0; m1 = mn1;
        float ls0 = 0.f, ls1 = 0.f;
        #pragma unroll
        for (int nf = 0; nf < 8; nf++) {
            float p;
            p = __expf(s[nf][0] - mn0); s[nf][0] = p; ls0 += p;
            p = __expf(s[nf][1] - mn0); s[nf][1] = p; ls0 += p;
            p = __expf(s[nf][2] - mn1); s[nf][2] = p; ls1 += p;
            p = __expf(s[nf][3] - mn1); s[nf][3] = p; ls1 += p;
        }
        ls0 += __shfl_xor_sync(0xffffffffu, ls0, 1);
        ls0 += __shfl_xor_sync(0xffffffffu, ls0, 2);
        ls1 += __shfl_xor_sync(0xffffffffu, ls1, 1);
        ls1 += __shfl_xor_sync(0xffffffffu, ls1, 2);
        l0 = l0 * corr0 + ls0;
        l1 = l1 * corr1 + ls1;
        #pragma unroll
        for (int nf = 0; nf < 8; nf++) {
            oA[nf][0] *= corr0; oA[nf][1] *= corr0;
            oA[nf][2] *= corr1; oA[nf][3] *= corr1;
        }

        // ---- O += P @ V (P fragments straight from registers) ----
        #pragma unroll
        for (int jc = 0; jc < 4; jc++) {
            uint32_t pah[4], pal[4];
            bsplit2(s[2 * jc][0],     s[2 * jc][1],     pah[0], pal[0]);
            bsplit2(s[2 * jc][2],     s[2 * jc][3],     pah[1], pal[1]);
            bsplit2(s[2 * jc + 1][0], s[2 * jc + 1][1], pah[2], pal[2]);
            bsplit2(s[2 * jc + 1][2], s[2 * jc + 1][3], pah[3], pal[3]);
            #pragma unroll
            for (int nf = 0; nf < 8; nf++) {
                int coln = nf * 8 + lg;
                uint32_t bh[2], bl[2];
                bh[0] = sVhi[(jc * 8 + lt) * VPAD + coln];
                bh[1] = sVhi[(jc * 8 + 4 + lt) * VPAD + coln];
                bl[0] = sVlo[(jc * 8 + lt) * VPAD + coln];
                bl[1] = sVlo[(jc * 8 + 4 + lt) * VPAD + coln];
                mma_bf16(oA[nf], pah, bh);
                mma_bf16(oA[nf], pah, bl);
                mma_bf16(oA[nf], pal, bh);
            }
        }
        __syncthreads();   // all reads done before next tile overwrites
    }

    float inv0 = 1.0f / l0, inv1 = 1.0f / l1;
    float* Op = O + ((size_t)(b * NS + qb * 64)) * ND + h * 64;
    #pragma unroll
    for (int nf = 0; nf < 8; nf++) {
        int d = nf * 8 + lt * 2;
        *(float2*)(Op + (size_t)r0 * ND + d) =
            make_float2(tf32r(oA[nf][0] * inv0), tf32r(oA[nf][1] * inv0));
        *(float2*)(Op + (size_t)r1 * ND + d) =
            make_float2(tf32r(oA[nf][2] * inv1), tf32r(oA[nf][3] * inv1));
    }
}

// ---------------------------------------------------------------------------
// LayerNorm
// ---------------------------------------------------------------------------
__global__ void ln_kernel(const float* __restrict__ X, const float* __restrict__ gam,
                          const float* __restrict__ bet, float* __restrict__ Yf,
                          float* __restrict__ Yr)
{
    int row  = blockIdx.x * 4 + (threadIdx.x >> 5);
    int lane = threadIdx.x & 31;
    const float* x = X + (size_t)row * ND;
    float4 v[4];
    float sum = 0.f;
    #pragma unroll
    for (int i = 0; i < 4; i++) {
        v[i] = *(const float4*)(x + lane * 4 + i * 128);
        sum += v[i].x + v[i].y + v[i].z + v[i].w;
    }
    #pragma unroll
    for (int off = 16; off; off >>= 1) sum += __shfl_xor_sync(0xffffffffu, sum, off);
    float mu = sum * (1.0f / 512.0f);
    float vs = 0.f;
    #pragma unroll
    for (int i = 0; i < 4; i++) {
        float dx;
        dx = v[i].x - mu; vs += dx * dx;
        dx = v[i].y - mu; vs += dx * dx;
        dx = v[i].z - mu; vs += dx * dx;
        dx = v[i].w - mu; vs += dx * dx;
    }
    #pragma unroll
    for (int off = 16; off; off >>= 1) vs += __shfl_xor_sync(0xffffffffu, vs, off);
    float rstd = rsqrtf(vs * (1.0f / 512.0f) + 1e-5f);
    float* yf = Yf + (size_t)row * ND;
    float* yr = Yr + (size_t)row * ND;
    #pragma unroll
    for (int i = 0; i < 4; i++) {
        float4 g4 = *(const float4*)(gam + lane * 4 + i * 128);
        float4 b4 = *(const float4*)(bet + lane * 4 + i * 128);
        float4 r;
        r.x = (v[i].x - mu) * rstd * g4.x + b4.x;
        r.y = (v[i].y - mu) * rstd * g4.y + b4.y;
        r.z = (v[i].z - mu) * rstd * g4.z + b4.z;
        r.w = (v[i].w - mu) * rstd * g4.w + b4.w;
        *(float4*)(yf + lane * 4 + i * 128) = r;
        float4 rr = make_float4(tf32r(r.x), tf32r(r.y), tf32r(r.z), tf32r(r.w));
        *(float4*)(yr + lane * 4 + i * 128) = rr;
    }
}

// ---------------------------------------------------------------------------
// Host orchestration
// ---------------------------------------------------------------------------
extern "C" void kernel_launch(void* const* d_in, const int* in_sizes, int n_in,
                              void* d_out, int out_size)
{
    const int*   ids  = (const int*)  d_in[0];
    const float* emb  = (const float*)d_in[1];
    const float* pe   = (const float*)d_in[2];
    const float* Wq   = (const float*)d_in[3];
    const float* bq   = (const float*)d_in[4];
    const float* Wk   = (const float*)d_in[5];
    const float* bk   = (const float*)d_in[6];
    const float* Wv   = (const float*)d_in[7];
    const float* bv   = (const float*)d_in[8];
    const float* Wo   = (const float*)d_in[9];
    const float* bo   = (const float*)d_in[10];
    const float* g1   = (const float*)d_in[11];
    const float* be1  = (const float*)d_in[12];
    const float* W1   = (const float*)d_in[13];
    const float* b1   = (const float*)d_in[14];
    const float* W2   = (const float*)d_in[15];
    const float* b2   = (const float*)d_in[16];
    const float* g2   = (const float*)d_in[17];
    const float* be2  = (const float*)d_in[18];
    const float* Wout = (const float*)d_in[19];
    const float* bout = (const float*)d_in[20];
    float* out = (float*)d_out;

    float* scratch = nullptr;
    cudaGetSymbolAddress((void**)&scratch, g_scratch);
    float* h      = scratch;
    float* h_r    = h      + SZ_HD;
    float* o      = h_r    + SZ_HD;
    float* tp     = o      + SZ_HD;
    float* qkv    = tp     + SZ_HD;
    float* ff     = qkv    + SZ_QKV;
    float* Wqkv_r = ff     + SZ_FF;
    float* Wo_r   = Wqkv_r + SZ_WQKV;
    float* W1_r   = Wo_r   + SZ_WO;
    float* W2_r   = W1_r   + SZ_W1;
    float* Wout_r = W2_r   + SZ_W2;
    float* bqkv   = Wout_r + SZ_WOUT;

    static bool attr_done = false;
    if (!attr_done) {
        cudaFuncSetAttribute(mma_gemm<false, false, false>,
                             cudaFuncAttributeMaxDynamicSharedMemorySize, GEMM_SMEM);
        cudaFuncSetAttribute(mma_gemm<false, true, false>,
                             cudaFuncAttributeMaxDynamicSharedMemorySize, GEMM_SMEM);
        cudaFuncSetAttribute(mma_gemm<true, false, true>,
                             cudaFuncAttributeMaxDynamicSharedMemorySize, GEMM_SMEM);
        cudaFuncSetAttribute(attn_mma,
                             cudaFuncAttributeMaxDynamicSharedMemorySize, ATTN_SMEM);
        attr_done = true;
    }

    pack_qkv_w<<<(int)(SZ_WQKV / 4 / 256), 256>>>(Wq, Wk, Wv, Wqkv_r);
    round_rest<<<(int)(SZ_REST / 4 / 256), 256>>>(Wo, W1, W2, Wout, bq, bk, bv, Wo_r);
    embed_kernel<<<(NM * ND / 4) / 256, 256>>>(ids, emb, pe, h, h_r);

    dim3 gQKV(1536 / 128, NM / 128);
    dim3 gP  (ND   / 128, NM / 128);
    dim3 gF1 (NF   / 128, NM / 128);
    dim3 attG(NS / 64, NH, NB);

    for (int L = 0; L < NL; L++) {
        size_t b_ = (size_t)L * ND;
        mma_gemm<false, false, false><<<gQKV, 512, GEMM_SMEM>>>(
            h_r, Wqkv_r + (size_t)L * 786432, bqkv + (size_t)L * 1536,
            nullptr, qkv, NM, 1536, ND);
        attn_mma<<<attG, 128, ATTN_SMEM>>>(qkv, o);
        mma_gemm<false, true, false><<<gP, 512, GEMM_SMEM>>>(
            o, Wo_r + (size_t)L * 262144, bo + b_, h, tp, NM, ND, ND);
        ln_kernel<<<NM / 4, 128>>>(tp, g1 + b_, be1 + b_, h, h_r);
        mma_gemm<true, false, true><<<gF1, 512, GEMM_SMEM>>>(
            h_r, W1_r + (size_t)L * 1048576, b1 + (size_t)L * NF,
            nullptr, ff, NM, NF, ND);
        mma_gemm<false, true, false><<<gP, 512, GEMM_SMEM>>>(
            ff, W2_r + (size_t)L * 1048576, b2 + b_, h, tp, NM, ND, NF);
        ln_kernel<<<NM / 4, 128>>>(tp, g2 + b_, be2 + b_, h, h_r);
    }
    mma_gemm<false, false, false><<<dim3(NV / 128, NM / 128), 512, GEMM_SMEM>>>(
        h_r, Wout_r, bout, nullptr, out, NM, NV, ND);
}